// round 1
// baseline (speedup 1.0000x reference)
#include <cuda_runtime.h>
#include <cuda_bf16.h>

// Problem constants (match reference)
#define BB   64
#define CC   2
#define LL   64
#define NBIN 16
#define NVOX (LL*LL*LL)        // 262144
#define NB2  (NBIN*NBIN)       // 256 bins
#define EPSV 1e-5f

// Scratch (no allocations allowed): bin table + per-(b,c) bin sums
__device__ unsigned char g_bins[NVOX];
__device__ float g_scratch[BB*CC*NB2];   // 32768 floats

// ---------------------------------------------------------------------------
// Kernel A: build the (voxel -> bin) table exactly as the reference does,
// and zero the scatter scratch. Runs every launch (graph-captured), ~2us.
// ---------------------------------------------------------------------------
__global__ __launch_bounds__(256) void build_tables_kernel() {
    int v = blockIdx.x * blockDim.x + threadIdx.x;
    if (v < NVOX) {
        float fi = (float)(v >> 12);
        float fj = (float)((v >> 6) & 63);
        float fk = (float)(v & 63);
        // exact integer squares -> exact f32 sums; __fsqrt_rn = correctly rounded
        float xc = __fsqrt_rn(fj*fj + fk*fk);
        float zc = __fsqrt_rn(fj*fj + fi*fi);
        const float deg = 57.29577951308232f;   // 180/pi, f32
        // mirror reference: floor(atan2(.,.) * deg / 22)
        float ra = __fdiv_rn(__fmul_rn(atan2f(xc, fi), deg), 22.0f);
        float rz = __fdiv_rn(__fmul_rn(atan2f(fk, zc), deg), 22.0f);
        int ax = (int)floorf(ra);
        int az = (int)floorf(rz);
        g_bins[v] = (unsigned char)(ax * NBIN + az);
    }
    if (v < BB*CC*NB2) g_scratch[v] = 0.0f;
}

// ---------------------------------------------------------------------------
// Kernel B: streaming weighted histogram.
//   For each (b,c) pair, sum x[v]*mag[v] into 256 bins.
//   - float4 coalesced loads of x, uchar4 loads of the bin table (L2 hits)
//   - mag recomputed inline (bit-exact with reference sqrt)
//   - per-lane run combining + warp segmented aggregation so shared atomics
//     are ~1-6 per 128 elements instead of 128 (avoids 32-way ATOMS conflicts)
// ---------------------------------------------------------------------------
#define SPLIT 16                      // blocks per (b,c) pair
#define BTHREADS 256

__global__ __launch_bounds__(BTHREADS) void accumulate_kernel(const float* __restrict__ x) {
    __shared__ float hist[NB2];
    const int t = threadIdx.x;
    const int lane = t & 31;
    for (int p = t; p < NB2; p += BTHREADS) hist[p] = 0.0f;
    __syncthreads();

    const int pair = blockIdx.x / SPLIT;     // b*C + c  (x layout is pair-major)
    const int part = blockIdx.x % SPLIT;
    const int chunk = NVOX / SPLIT;          // 16384 elements
    const int base_v = part * chunk;
    const float* xp = x + (size_t)pair * NVOX;
    const unsigned full = 0xffffffffu;

    for (int off = t * 4; off < chunk; off += BTHREADS * 4) {
        int v = base_v + off;
        float4 xv = *reinterpret_cast<const float4*>(xp + v);
        uchar4 bq = *reinterpret_cast<const uchar4*>(g_bins + v);

        float fi = (float)(v >> 12);
        float fj = (float)((v >> 6) & 63);
        float fk = (float)(v & 63);          // v%4==0 so k..k+3 stay in-row
        float s2 = fi*fi + fj*fj;
        float m0 = __fsqrt_rn(s2 + fk*fk);
        float m1 = __fsqrt_rn(s2 + (fk+1.0f)*(fk+1.0f));
        float m2 = __fsqrt_rn(s2 + (fk+2.0f)*(fk+2.0f));
        float m3 = __fsqrt_rn(s2 + (fk+3.0f)*(fk+3.0f));

        float v0 = xv.x * m0, v1 = xv.y * m1, v2 = xv.z * m2, v3 = xv.w * m3;
        int b0 = bq.x, b1 = bq.y, b2 = bq.z, b3 = bq.w;

        // per-lane run combine (bins are piecewise constant along k)
        float acc = v0; int cur = b0;
        if (b1 == cur) acc += v1; else { atomicAdd(&hist[cur], acc); cur = b1; acc = v1; }
        if (b2 == cur) acc += v2; else { atomicAdd(&hist[cur], acc); cur = b2; acc = v2; }
        if (b3 == cur) acc += v3; else { atomicAdd(&hist[cur], acc); cur = b3; acc = v3; }

        // warp segmented aggregation: group adjacent lanes with equal bin
        int prev = __shfl_up_sync(full, cur, 1);
        bool head = (lane == 0) || (prev != cur);
        unsigned hm = __ballot_sync(full, head);

        // plain inclusive scan of acc
        float sc = acc;
        #pragma unroll
        for (int d = 1; d < 32; d <<= 1) {
            float y = __shfl_up_sync(full, sc, d);
            if (lane >= d) sc += y;
        }
        // segment start = highest head bit <= lane (bit 0 always set)
        unsigned below = hm & (0xffffffffu >> (31 - lane));
        int st = 31 - __clz(below);
        bool endl = (lane == 31) || ((hm >> (lane + 1)) & 1u);
        float before = __shfl_sync(full, sc, (st > 0) ? (st - 1) : 0);
        float total = sc - ((st > 0) ? before : 0.0f);
        if (endl) atomicAdd(&hist[cur], total);
    }

    __syncthreads();
    for (int p = t; p < NB2; p += BTHREADS) {
        float val = hist[p];
        if (val != 0.0f) atomicAdd(&g_scratch[pair * NB2 + p], val);
    }
}

// ---------------------------------------------------------------------------
// Kernel C: per-channel group norm over (B, N, N) = 16384 values per channel.
// Two-pass (mean, then var) to match reference numerics. One block per channel.
// ---------------------------------------------------------------------------
__global__ __launch_bounds__(512) void gn_kernel(const float* __restrict__ gamma,
                                                 const float* __restrict__ beta,
                                                 float* __restrict__ out) {
    const int c = blockIdx.x;
    const int t = threadIdx.x;          // 512 threads
    const int lane = t & 31, warp = t >> 5;
    const unsigned full = 0xffffffffu;

    __shared__ float red[16];
    __shared__ float s_mean, s_rs;

    float vals[32];
    float sum = 0.0f;
    #pragma unroll
    for (int i = 0; i < 32; i++) {
        int idx = i * 512 + t;                       // coalesced
        int b = idx >> 8, p = idx & 255;
        float g = g_scratch[(b * CC + c) * NB2 + p];
        vals[i] = g;
        sum += g;
    }
    #pragma unroll
    for (int d = 16; d; d >>= 1) sum += __shfl_down_sync(full, sum, d);
    if (lane == 0) red[warp] = sum;
    __syncthreads();
    if (t == 0) {
        float tot = 0.0f;
        #pragma unroll
        for (int w = 0; w < 16; w++) tot += red[w];
        s_mean = tot * (1.0f / 16384.0f);
    }
    __syncthreads();
    float mean = s_mean;

    float vs = 0.0f;
    #pragma unroll
    for (int i = 0; i < 32; i++) {
        float d = vals[i] - mean;
        vs = fmaf(d, d, vs);
    }
    #pragma unroll
    for (int d = 16; d; d >>= 1) vs += __shfl_down_sync(full, vs, d);
    __syncthreads();                     // red[] reuse
    if (lane == 0) red[warp] = vs;
    __syncthreads();
    if (t == 0) {
        float tot = 0.0f;
        #pragma unroll
        for (int w = 0; w < 16; w++) tot += red[w];
        float var = tot * (1.0f / 16384.0f);
        s_rs = rsqrtf(var + EPSV);
    }
    __syncthreads();
    float rs = s_rs;
    float ga = gamma[c], be = beta[c];

    #pragma unroll
    for (int i = 0; i < 32; i++) {
        int idx = i * 512 + t;
        int b = idx >> 8, p = idx & 255;
        out[(b * CC + c) * NB2 + p] = (vals[i] - mean) * rs * ga + be;
    }
}

// ---------------------------------------------------------------------------
extern "C" void kernel_launch(void* const* d_in, const int* in_sizes, int n_in,
                              void* d_out, int out_size) {
    const float* x     = (const float*)d_in[0];   // [64, 2*64^3]
    const float* gamma = (const float*)d_in[1];   // [2]
    const float* beta  = (const float*)d_in[2];   // [2]
    float* out = (float*)d_out;                   // [64,2,16,16] f32

    build_tables_kernel<<<(NVOX + 255) / 256, 256>>>();
    accumulate_kernel<<<BB * CC * SPLIT, BTHREADS>>>(x);
    gn_kernel<<<CC, 512>>>(gamma, beta, out);
}